// round 7
// baseline (speedup 1.0000x reference)
#include <cuda_runtime.h>
#include <cuda_bf16.h>
#include <math.h>
#include <float.h>
#include <stdint.h>

// Problem constants
#define BATCH 32
#define LSEQ  2048
#define EDIM  1024
#define NHEAD 16
#define DHEAD 64
#define HD    (NHEAD * DHEAD)     // 1024
#define ROWS  (BATCH * LSEQ)      // 65536
#define FLAT  (LSEQ * EDIM)       // 2097152
#define NCLS  2

#define SMEM_SWIZZLE_128B(byte_offset) \
    ((byte_offset) ^ (((byte_offset) >> 3) & 0x70))

__device__ __forceinline__ uint32_t smem_to_u32(const void* smem_ptr) {
    uint32_t addr;
    asm("{ .reg .u64 tmp; cvta.to.shared.u64 tmp, %1; cvt.u32.u64 %0, tmp; }"
        : "=r"(addr) : "l"(smem_ptr));
    return addr;
}

__device__ __forceinline__ void cp_async16(uint32_t smem_addr, const void* gptr) {
    asm volatile("cp.async.cg.shared.global [%0], [%1], 16;"
                 :: "r"(smem_addr), "l"(gptr) : "memory");
}
__device__ __forceinline__ void cp_commit() {
    asm volatile("cp.async.commit_group;" ::: "memory");
}

__device__ __forceinline__ void ldmx4(uint32_t* r, uint32_t addr) {
    asm volatile("ldmatrix.sync.aligned.m8n8.x4.shared.b16 {%0,%1,%2,%3}, [%4];"
                 : "=r"(r[0]), "=r"(r[1]), "=r"(r[2]), "=r"(r[3]) : "r"(addr));
}
__device__ __forceinline__ void ldmx4t(uint32_t* r, uint32_t addr) {
    asm volatile("ldmatrix.sync.aligned.m8n8.x4.trans.shared.b16 {%0,%1,%2,%3}, [%4];"
                 : "=r"(r[0]), "=r"(r[1]), "=r"(r[2]), "=r"(r[3]) : "r"(addr));
}

__device__ __forceinline__ void mma16816(float* c, const uint32_t* a, const uint32_t* b) {
    asm volatile(
        "mma.sync.aligned.m16n8k16.row.col.f32.bf16.bf16.f32 "
        "{%0,%1,%2,%3}, {%4,%5,%6,%7}, {%8,%9}, {%0,%1,%2,%3};"
        : "+f"(c[0]), "+f"(c[1]), "+f"(c[2]), "+f"(c[3])
        : "r"(a[0]), "r"(a[1]), "r"(a[2]), "r"(a[3]), "r"(b[0]), "r"(b[1]));
}

// ---------------------------------------------------------------------------
// Device-global scratch
// ---------------------------------------------------------------------------
__device__ __nv_bfloat16 g_hb[(size_t)ROWS * EDIM];     // 128 MB
__device__ __nv_bfloat16 g_qb[(size_t)ROWS * HD];       // q, then att (in place)
__device__ __nv_bfloat16 g_kb[(size_t)ROWS * HD];
__device__ __nv_bfloat16 g_vb[(size_t)ROWS * HD];
__device__ __nv_bfloat16 g_ob[(size_t)ROWS * EDIM];
__device__ __nv_bfloat16 g_wqkv[(size_t)3 * HD * EDIM]; // fused Wq^T|Wk^T|Wv^T
__device__ __nv_bfloat16 g_wo[(size_t)EDIM * HD];
__device__ double g_logits[BATCH * NCLS];

// ---------------------------------------------------------------------------
// 1) Embedding gather -> bf16
// ---------------------------------------------------------------------------
__global__ __launch_bounds__(256) void gather_kernel(
    const int* __restrict__ x, const float* __restrict__ emb)
{
    int row = blockIdx.x;
    int v = x[row];
    int t = threadIdx.x;
    float4 f = ((const float4*)(emb + (size_t)v * EDIM))[t];
    __nv_bfloat162 lo = __floats2bfloat162_rn(f.x, f.y);
    __nv_bfloat162 hi = __floats2bfloat162_rn(f.z, f.w);
    uint2 p;
    p.x = *(uint32_t*)&lo;
    p.y = *(uint32_t*)&hi;
    ((uint2*)(g_hb + (size_t)row * EDIM))[t] = p;
}

// ---------------------------------------------------------------------------
// 1b) Fused weight transpose + convert (grid.z selects which weight)
// ---------------------------------------------------------------------------
__global__ __launch_bounds__(256) void transpose_all_kernel(
    const float* __restrict__ Wq, const float* __restrict__ Wkv,
    const float* __restrict__ Wo,
    __nv_bfloat16* __restrict__ wqkv, __nv_bfloat16* __restrict__ wo)
{
    __shared__ float tile[32][33];
    const float* in; int ldin, coloff; __nv_bfloat16* out;
    switch (blockIdx.z) {
        case 0: in = Wq;  ldin = HD;     coloff = 0;  out = wqkv;                         break;
        case 1: in = Wkv; ldin = 2 * HD; coloff = 0;  out = wqkv + (size_t)HD * EDIM;     break;
        case 2: in = Wkv; ldin = 2 * HD; coloff = HD; out = wqkv + (size_t)2 * HD * EDIM; break;
        default: in = Wo; ldin = EDIM;   coloff = 0;  out = wo;                           break;
    }
    int bx = blockIdx.x * 32;  // n block
    int by = blockIdx.y * 32;  // k block
    int tx = threadIdx.x & 31;
    int ty = threadIdx.x >> 5;
    for (int i = ty; i < 32; i += 8)
        tile[i][tx] = in[(size_t)(by + i) * ldin + coloff + bx + tx];
    __syncthreads();
    for (int i = ty; i < 32; i += 8)
        out[(size_t)(bx + i) * 1024 + by + tx] = __float2bfloat16(tile[tx][i]);
}

// ---------------------------------------------------------------------------
// 2) bf16 tensor-core GEMM (mma.sync). CTA tile 128x256, 512 threads
//    (16 warps, warp tile 32x64), 4-stage cp.async ring.
// ---------------------------------------------------------------------------
#define MT 128
#define NT 256
#define GTHREADS 512
#define A_BYTES (MT * 128)          // 16 KB per K-chunk of 64
#define B_BYTES (NT * 128)          // 32 KB
#define NCHUNKS 16
#define STAGES 4
#define GEMM_SMEM (STAGES * (A_BYTES + B_BYTES) + 1024)   // 197632

__device__ __forceinline__ void load_chunk(
    uint32_t abuf, uint32_t bbuf,
    const char* Abase, const char* Bbase, int c, int t)
{
#pragma unroll
    for (int i = 0; i < 2; i++) {                     // A: 1024 segs / 512 thr
        int seg = t + GTHREADS * i;
        int r = seg >> 3, s = seg & 7;
        uint32_t off = SMEM_SWIZZLE_128B((uint32_t)(r * 128 + s * 16));
        cp_async16(abuf + off, Abase + (size_t)r * 2048 + c * 128 + s * 16);
    }
#pragma unroll
    for (int i = 0; i < 4; i++) {                     // B: 2048 segs / 512 thr
        int seg = t + GTHREADS * i;
        int r = seg >> 3, s = seg & 7;
        uint32_t off = SMEM_SWIZZLE_128B((uint32_t)(r * 128 + s * 16));
        cp_async16(bbuf + off, Bbase + (size_t)r * 2048 + c * 128 + s * 16);
    }
}

template<bool RES>
__global__ __launch_bounds__(GTHREADS, 1) void gemm_bf16_kernel(
    const __nv_bfloat16* __restrict__ A,
    const __nv_bfloat16* __restrict__ Bt,
    const __nv_bfloat16* __restrict__ Res,
    __nv_bfloat16* __restrict__ D0,
    __nv_bfloat16* __restrict__ D1,
    __nv_bfloat16* __restrict__ D2)
{
    extern __shared__ char smem[];
    uint32_t base = (smem_to_u32(smem) + 1023) & ~1023u;
    uint32_t a_sm[STAGES], b_sm[STAGES];
#pragma unroll
    for (int s = 0; s < STAGES; s++) {
        a_sm[s] = base + s * (A_BYTES + B_BYTES);
        b_sm[s] = a_sm[s] + A_BYTES;
    }

    int t = threadIdx.x;
    int wid = t >> 5, lane = t & 31;
    int mwarp0 = (wid & 3) * 32;        // 4 m-warps -> 128
    int nwarp0 = (wid >> 2) * 64;       // 4 n-warps -> 256
    size_t row0 = (size_t)blockIdx.y * MT;
    int col0 = blockIdx.x * NT;

    // output buffer selection (fused QKV; NT divides 1024 so no straddle)
    int tgt = col0 >> 10;
    int colc = col0 & 1023;
    __nv_bfloat16* D = (tgt == 0) ? D0 : ((tgt == 1) ? D1 : D2);

    const char* Abase = (const char*)(A + row0 * 1024);
    const char* Bbase = (const char*)(Bt + (size_t)col0 * 1024);

    // per-lane ldmatrix address components
    int g = lane & 7, sel = lane >> 3;
    int mA = mwarp0 + g + (sel & 1) * 8;
    uint32_t aRow[2] = { (uint32_t)(mA * 128), (uint32_t)((mA + 16) * 128) };
    uint32_t aKb = (uint32_t)((sel >> 1) * 16);
    uint32_t aX  = (uint32_t)((mA & 7) << 4);

    int nB = nwarp0 + g + ((sel >> 1) * 8);
    uint32_t bRow[4] = { (uint32_t)(nB * 128), (uint32_t)((nB + 16) * 128),
                         (uint32_t)((nB + 32) * 128), (uint32_t)((nB + 48) * 128) };
    uint32_t bKb = (uint32_t)((sel & 1) * 16);
    uint32_t bX  = (uint32_t)((nB & 7) << 4);

    float acc[2][8][4];
#pragma unroll
    for (int i = 0; i < 2; i++)
#pragma unroll
        for (int j = 0; j < 8; j++)
#pragma unroll
            for (int k = 0; k < 4; k++) acc[i][j][k] = 0.f;

    // prologue: prime 3 stages
    load_chunk(a_sm[0], b_sm[0], Abase, Bbase, 0, t); cp_commit();
    load_chunk(a_sm[1], b_sm[1], Abase, Bbase, 1, t); cp_commit();
    load_chunk(a_sm[2], b_sm[2], Abase, Bbase, 2, t); cp_commit();

    int stage = 0;
    for (int c = 0; c < NCHUNKS; c++) {
        if (c < NCHUNKS - 3) {
            asm volatile("cp.async.wait_group 2;" ::: "memory");
        } else {
            asm volatile("cp.async.wait_group 0;" ::: "memory");
        }
        __syncthreads();
        if (c + 3 < NCHUNKS) {
            int ns = stage + 3; if (ns >= STAGES) ns -= STAGES;
            load_chunk(a_sm[ns], b_sm[ns], Abase, Bbase, c + 3, t);
            cp_commit();
        }

        uint32_t ab = a_sm[stage], bb = b_sm[stage];
#pragma unroll
        for (int s = 0; s < 4; s++) {         // 4 k16 steps per chunk
            uint32_t kb0 = (uint32_t)(s * 32);
            uint32_t afrag[2][4], bfrag[4][4];
#pragma unroll
            for (int mi = 0; mi < 2; mi++)
                ldmx4(afrag[mi], ab + aRow[mi] + ((aKb + kb0) ^ aX));
#pragma unroll
            for (int j = 0; j < 4; j++)
                ldmx4(bfrag[j], bb + bRow[j] + ((bKb + kb0) ^ bX));
#pragma unroll
            for (int mi = 0; mi < 2; mi++)
#pragma unroll
                for (int j = 0; j < 4; j++) {
                    mma16816(acc[mi][2 * j],     afrag[mi], &bfrag[j][0]);
                    mma16816(acc[mi][2 * j + 1], afrag[mi], &bfrag[j][2]);
                }
        }
        stage++; if (stage >= STAGES) stage -= STAGES;
    }

    // Epilogue
#pragma unroll
    for (int mi = 0; mi < 2; mi++) {
        size_t r0 = row0 + mwarp0 + mi * 16 + (lane >> 2);
#pragma unroll
        for (int nj = 0; nj < 8; nj++) {
            int col = colc + nwarp0 + nj * 8 + (lane & 3) * 2;
            float c0 = acc[mi][nj][0], c1 = acc[mi][nj][1];
            float c2 = acc[mi][nj][2], c3 = acc[mi][nj][3];
            if (RES) {
                uint32_t u0 = *(const uint32_t*)(Res + r0 * 1024 + col);
                uint32_t u1 = *(const uint32_t*)(Res + (r0 + 8) * 1024 + col);
                float2 f0 = __bfloat1622float2(*(__nv_bfloat162*)&u0);
                float2 f1 = __bfloat1622float2(*(__nv_bfloat162*)&u1);
                c0 += f0.x; c1 += f0.y; c2 += f1.x; c3 += f1.y;
            }
            __nv_bfloat162 h0 = __floats2bfloat162_rn(c0, c1);
            __nv_bfloat162 h1 = __floats2bfloat162_rn(c2, c3);
            *(uint32_t*)(D + r0 * 1024 + col)       = *(uint32_t*)&h0;
            *(uint32_t*)(D + (r0 + 8) * 1024 + col) = *(uint32_t*)&h1;
        }
    }
}

// ---------------------------------------------------------------------------
// 3) Attention on tensor cores. One warp per (l, n) pair.
// ---------------------------------------------------------------------------
#define ATT_WARPS 8
#define ATT_SMEM (ATT_WARPS * 3 * 4096)   // 96 KB
#define ROWSTRIDE_B (LSEQ * NHEAD * DHEAD * 2)  // batch-row stride in bytes

__global__ __launch_bounds__(256) void attn_kernel()
{
    extern __shared__ char asmem[];
    int t = threadIdx.x, w = t >> 5, lane = t & 31;
    uint32_t wbase = smem_to_u32(asmem) + w * 12288;
    uint32_t qsm = wbase, ksm = wbase + 4096, vsm = wbase + 8192;

    int pair = blockIdx.x * ATT_WARPS + w;
    int l = pair >> 4, n = pair & 15;
    size_t ebase = ((size_t)l * NHEAD + n) * DHEAD;
    const char* qg = (const char*)(g_qb + ebase);
    const char* kg = (const char*)(g_kb + ebase);
    const char* vg = (const char*)(g_vb + ebase);

#pragma unroll
    for (int i = 0; i < 8; i++) {
        int s = lane + 32 * i;
        int row = s >> 3, sub = s & 7;
        size_t go = (size_t)row * ROWSTRIDE_B + sub * 16;
        uint32_t so = SMEM_SWIZZLE_128B((uint32_t)(row * 128 + sub * 16));
        cp_async16(qsm + so, qg + go);
        cp_async16(ksm + so, kg + go);
        cp_async16(vsm + so, vg + go);
    }
    cp_commit();
    asm volatile("cp.async.wait_group 0;" ::: "memory");
    __syncwarp();

    int g8 = lane & 7, sel = lane >> 3;

    // ---- S = Q K^T ----
    float c[2][4][4];
#pragma unroll
    for (int mi = 0; mi < 2; mi++)
#pragma unroll
        for (int j = 0; j < 4; j++)
#pragma unroll
            for (int k = 0; k < 4; k++) c[mi][j][k] = 0.f;

#pragma unroll
    for (int kc = 0; kc < 4; kc++) {
        uint32_t kb = kc * 32;
        uint32_t af[2][4], bfr[2][4];
#pragma unroll
        for (int mi = 0; mi < 2; mi++) {
            int row = mi * 16 + g8 + (sel & 1) * 8;
            uint32_t off = row * 128 + ((kb + (sel >> 1) * 16) ^ ((row & 7) << 4));
            ldmx4(af[mi], qsm + off);
        }
#pragma unroll
        for (int nj2 = 0; nj2 < 2; nj2++) {
            int row = nj2 * 16 + g8 + (sel >> 1) * 8;
            uint32_t off = row * 128 + ((kb + (sel & 1) * 16) ^ ((row & 7) << 4));
            ldmx4(bfr[nj2], ksm + off);
        }
#pragma unroll
        for (int mi = 0; mi < 2; mi++)
#pragma unroll
            for (int nj2 = 0; nj2 < 2; nj2++) {
                mma16816(c[mi][2 * nj2],     af[mi], &bfr[nj2][0]);
                mma16816(c[mi][2 * nj2 + 1], af[mi], &bfr[nj2][2]);
            }
    }

    // ---- softmax ----
    float inv0[2], inv1[2];
#pragma unroll
    for (int mi = 0; mi < 2; mi++) {
        float m0 = -FLT_MAX, m1 = -FLT_MAX;
#pragma unroll
        for (int j = 0; j < 4; j++) {
#pragma unroll
            for (int k = 0; k < 4; k++) c[mi][j][k] *= 0.125f;
            m0 = fmaxf(m0, fmaxf(c[mi][j][0], c[mi][j][1]));
            m1 = fmaxf(m1, fmaxf(c[mi][j][2], c[mi][j][3]));
        }
        m0 = fmaxf(m0, __shfl_xor_sync(0xffffffffu, m0, 1));
        m0 = fmaxf(m0, __shfl_xor_sync(0xffffffffu, m0, 2));
        m1 = fmaxf(m1, __shfl_xor_sync(0xffffffffu, m1, 1));
        m1 = fmaxf(m1, __shfl_xor_sync(0xffffffffu, m1, 2));
        float s0 = 0.f, s1 = 0.f;
#pragma unroll
        for (int j = 0; j < 4; j++) {
            c[mi][j][0] = __expf(c[mi][j][0] - m0);
            c[mi][j][1] = __expf(c[mi][j][1] - m0);
            c[mi][j][2] = __expf(c[mi][j][2] - m1);
            c[mi][j][3] = __expf(c[mi][j][3] - m1);
            s0 += c[mi][j][0] + c[mi][j][1];
            s1 += c[mi][j][2] + c[mi][j][3];
        }
        s0 += __shfl_xor_sync(0xffffffffu, s0, 1);
        s0 += __shfl_xor_sync(0xffffffffu, s0, 2);
        s1 += __shfl_xor_sync(0xffffffffu, s1, 1);
        s1 += __shfl_xor_sync(0xffffffffu, s1, 2);
        inv0[mi] = 1.f / s0;
        inv1[mi] = 1.f / s1;
    }

    // ---- pack P ----
    uint32_t pf[2][2][4];
#pragma unroll
    for (int mi = 0; mi < 2; mi++)
#pragma unroll
        for (int kc = 0; kc < 2; kc++) {
            __nv_bfloat162 x0 = __floats2bfloat162_rn(c[mi][2 * kc][0],     c[mi][2 * kc][1]);
            __nv_bfloat162 x1 = __floats2bfloat162_rn(c[mi][2 * kc][2],     c[mi][2 * kc][3]);
            __nv_bfloat162 x2 = __floats2bfloat162_rn(c[mi][2 * kc + 1][0], c[mi][2 * kc + 1][1]);
            __nv_bfloat162 x3 = __floats2bfloat162_rn(c[mi][2 * kc + 1][2], c[mi][2 * kc + 1][3]);
            pf[mi][kc][0] = *(uint32_t*)&x0;
            pf[mi][kc][1] = *(uint32_t*)&x1;
            pf[mi][kc][2] = *(uint32_t*)&x2;
            pf[mi][kc][3] = *(uint32_t*)&x3;
        }

    // ---- att = P V ----
    float cv[2][8][4];
#pragma unroll
    for (int mi = 0; mi < 2; mi++)
#pragma unroll
        for (int j = 0; j < 8; j++)
#pragma unroll
            for (int k = 0; k < 4; k++) cv[mi][j][k] = 0.f;

#pragma unroll
    for (int kc = 0; kc < 2; kc++) {
#pragma unroll
        for (int dj2 = 0; dj2 < 4; dj2++) {
            int row = kc * 16 + g8 + (sel & 1) * 8;
            uint32_t colb = dj2 * 32 + (sel >> 1) * 16;
            uint32_t off = row * 128 + (colb ^ ((row & 7) << 4));
            uint32_t bv[4];
            ldmx4t(bv, vsm + off);
#pragma unroll
            for (int mi = 0; mi < 2; mi++) {
                mma16816(cv[mi][2 * dj2],     pf[mi][kc], &bv[0]);
                mma16816(cv[mi][2 * dj2 + 1], pf[mi][kc], &bv[2]);
            }
        }
    }

    // ---- normalize + store ----
    int r = lane >> 2, cq = (lane & 3) * 2;
#pragma unroll
    for (int mi = 0; mi < 2; mi++) {
        int i0 = mi * 16 + r;
        __nv_bfloat16* o0 = g_qb + ebase + (size_t)i0 * (LSEQ * NHEAD * DHEAD);
        __nv_bfloat16* o1 = o0 + (size_t)8 * (LSEQ * NHEAD * DHEAD);
#pragma unroll
        for (int dj = 0; dj < 8; dj++) {
            int col = dj * 8 + cq;
            __nv_bfloat162 h0 = __floats2bfloat162_rn(cv[mi][dj][0] * inv0[mi],
                                                      cv[mi][dj][1] * inv0[mi]);
            __nv_bfloat162 h1 = __floats2bfloat162_rn(cv[mi][dj][2] * inv1[mi],
                                                      cv[mi][dj][3] * inv1[mi]);
            *(uint32_t*)(o0 + col) = *(uint32_t*)&h0;
            *(uint32_t*)(o1 + col) = *(uint32_t*)&h1;
        }
    }
}

// ---------------------------------------------------------------------------
// 4) Logits
// ---------------------------------------------------------------------------
__global__ void zero_logits_kernel()
{
    if (threadIdx.x < BATCH * NCLS) g_logits[threadIdx.x] = 0.0;
}

__global__ __launch_bounds__(256) void logits_kernel(const float* __restrict__ Wf)
{
    const int CHUNK = 512;
    int i0 = blockIdx.x * CHUNK;
    int t = threadIdx.x;

    float acc[64];
#pragma unroll
    for (int k = 0; k < 64; k++) acc[k] = 0.f;

    for (int s = 0; s < CHUNK; s += 256) {
        int ii = i0 + s + t;
        float w0 = Wf[(size_t)ii * 2];
        float w1 = Wf[(size_t)ii * 2 + 1];
#pragma unroll
        for (int b = 0; b < 32; b++) {
            float v = __bfloat162float(g_ob[(size_t)b * FLAT + ii]);
            acc[2 * b]     += v * w0;
            acc[2 * b + 1] += v * w1;
        }
    }

#pragma unroll
    for (int k = 0; k < 64; k++) {
        float v = acc[k];
        v += __shfl_down_sync(0xffffffffu, v, 16);
        v += __shfl_down_sync(0xffffffffu, v, 8);
        v += __shfl_down_sync(0xffffffffu, v, 4);
        v += __shfl_down_sync(0xffffffffu, v, 2);
        v += __shfl_down_sync(0xffffffffu, v, 1);
        acc[k] = v;
    }

    __shared__ float sacc[64];
    if (t < 64) sacc[t] = 0.f;
    __syncthreads();
    if ((t & 31) == 0) {
#pragma unroll
        for (int k = 0; k < 64; k++) atomicAdd(&sacc[k], acc[k]);
    }
    __syncthreads();
    if (t < 64) atomicAdd(&g_logits[t], (double)sacc[t]);
}

// ---------------------------------------------------------------------------
// 5) Loss
// ---------------------------------------------------------------------------
__global__ void loss_kernel(const int* __restrict__ y,
                            const float* __restrict__ bf,
                            float* __restrict__ out)
{
    if (threadIdx.x != 0 || blockIdx.x != 0) return;
    double s = 0.0;
    double b0 = (double)bf[0], b1 = (double)bf[1];
    for (int b = 0; b < BATCH; b++) {
        double l0 = g_logits[2 * b]     + b0;
        double l1 = g_logits[2 * b + 1] + b1;
        double m  = l0 > l1 ? l0 : l1;
        double lse = m + log(exp(l0 - m) + exp(l1 - m));
        double lp  = (y[b] == 0 ? l0 : l1) - lse;
        s += lp;
    }
    out[0] = (float)(-s / (double)BATCH);
}

// ---------------------------------------------------------------------------
// Launch
// ---------------------------------------------------------------------------
extern "C" void kernel_launch(void* const* d_in, const int* in_sizes, int n_in,
                              void* d_out, int out_size)
{
    const int*   x     = (const int*)d_in[0];
    const int*   y     = (const int*)d_in[1];
    const float* emb   = (const float*)d_in[2];
    const float* Wq    = (const float*)d_in[3];
    const float* Wkv   = (const float*)d_in[4];
    const float* Wo    = (const float*)d_in[5];
    const float* Wf    = (const float*)d_in[6];
    const float* bf    = (const float*)d_in[7];
    float* out = (float*)d_out;

    __nv_bfloat16 *p_hb, *p_qb, *p_kb, *p_vb, *p_ob, *p_wqkv, *p_wo;
    cudaGetSymbolAddress((void**)&p_hb,   g_hb);
    cudaGetSymbolAddress((void**)&p_qb,   g_qb);
    cudaGetSymbolAddress((void**)&p_kb,   g_kb);
    cudaGetSymbolAddress((void**)&p_vb,   g_vb);
    cudaGetSymbolAddress((void**)&p_ob,   g_ob);
    cudaGetSymbolAddress((void**)&p_wqkv, g_wqkv);
    cudaGetSymbolAddress((void**)&p_wo,   g_wo);

    cudaFuncSetAttribute(gemm_bf16_kernel<false>,
                         cudaFuncAttributeMaxDynamicSharedMemorySize, GEMM_SMEM);
    cudaFuncSetAttribute(gemm_bf16_kernel<true>,
                         cudaFuncAttributeMaxDynamicSharedMemorySize, GEMM_SMEM);
    cudaFuncSetAttribute(attn_kernel,
                         cudaFuncAttributeMaxDynamicSharedMemorySize, ATT_SMEM);

    // 1) gather + fused weight prep
    gather_kernel<<<ROWS, 256>>>(x, emb);
    dim3 tgrid(32, 32, 4), tblk(256);
    transpose_all_kernel<<<tgrid, tblk>>>(Wq, Wkv, Wo, p_wqkv, p_wo);

    // 2) fused QKV projection: one GEMM, N = 3072
    dim3 qkvgrid(3 * EDIM / NT, ROWS / MT);  // (12, 512)
    gemm_bf16_kernel<false><<<qkvgrid, GTHREADS, GEMM_SMEM>>>(
        p_hb, p_wqkv, nullptr, p_qb, p_kb, p_vb);

    // 3) attention (tensor cores; in place: g_qb <- att)
    attn_kernel<<<LSEQ * NHEAD / ATT_WARPS, 256, ATT_SMEM>>>();

    // 4) out = h + att @ Wo
    dim3 ogrid(EDIM / NT, ROWS / MT);        // (4, 512)
    gemm_bf16_kernel<true><<<ogrid, GTHREADS, GEMM_SMEM>>>(
        p_qb, p_wo, p_hb, p_ob, p_ob, p_ob);

    // 5) logits + loss
    zero_logits_kernel<<<1, 64>>>();
    logits_kernel<<<FLAT / 512, 256>>>(Wf);
    loss_kernel<<<1, 32>>>(y, bf, out);
}

// round 8
// speedup vs baseline: 1.6699x; 1.6699x over previous
#include <cuda_runtime.h>
#include <cuda_bf16.h>
#include <math.h>
#include <float.h>
#include <stdint.h>

// Problem constants
#define BATCH 32
#define LSEQ  2048
#define EDIM  1024
#define NHEAD 16
#define DHEAD 64
#define HD    (NHEAD * DHEAD)     // 1024
#define ROWS  (BATCH * LSEQ)      // 65536
#define FLAT  (LSEQ * EDIM)       // 2097152
#define NCLS  2

#define SMEM_SWIZZLE_128B(byte_offset) \
    ((byte_offset) ^ (((byte_offset) >> 3) & 0x70))

__device__ __forceinline__ uint32_t smem_to_u32(const void* smem_ptr) {
    uint32_t addr;
    asm("{ .reg .u64 tmp; cvta.to.shared.u64 tmp, %1; cvt.u32.u64 %0, tmp; }"
        : "=r"(addr) : "l"(smem_ptr));
    return addr;
}

__device__ __forceinline__ void cp_async16(uint32_t smem_addr, const void* gptr) {
    asm volatile("cp.async.cg.shared.global [%0], [%1], 16;"
                 :: "r"(smem_addr), "l"(gptr) : "memory");
}
__device__ __forceinline__ void cp_commit() {
    asm volatile("cp.async.commit_group;" ::: "memory");
}

__device__ __forceinline__ void ldmx4(uint32_t* r, uint32_t addr) {
    asm volatile("ldmatrix.sync.aligned.m8n8.x4.shared.b16 {%0,%1,%2,%3}, [%4];"
                 : "=r"(r[0]), "=r"(r[1]), "=r"(r[2]), "=r"(r[3]) : "r"(addr));
}
__device__ __forceinline__ void ldmx4t(uint32_t* r, uint32_t addr) {
    asm volatile("ldmatrix.sync.aligned.m8n8.x4.trans.shared.b16 {%0,%1,%2,%3}, [%4];"
                 : "=r"(r[0]), "=r"(r[1]), "=r"(r[2]), "=r"(r[3]) : "r"(addr));
}

__device__ __forceinline__ void mma16816(float* c, const uint32_t* a, const uint32_t* b) {
    asm volatile(
        "mma.sync.aligned.m16n8k16.row.col.f32.bf16.bf16.f32 "
        "{%0,%1,%2,%3}, {%4,%5,%6,%7}, {%8,%9}, {%0,%1,%2,%3};"
        : "+f"(c[0]), "+f"(c[1]), "+f"(c[2]), "+f"(c[3])
        : "r"(a[0]), "r"(a[1]), "r"(a[2]), "r"(a[3]), "r"(b[0]), "r"(b[1]));
}

// ---------------------------------------------------------------------------
// Device-global scratch
// ---------------------------------------------------------------------------
__device__ __nv_bfloat16 g_hb[(size_t)ROWS * EDIM];     // 128 MB
__device__ __nv_bfloat16 g_qb[(size_t)ROWS * HD];       // q, then att (in place)
__device__ __nv_bfloat16 g_kb[(size_t)ROWS * HD];
__device__ __nv_bfloat16 g_vb[(size_t)ROWS * HD];
__device__ __nv_bfloat16 g_ob[(size_t)ROWS * EDIM];
__device__ __nv_bfloat16 g_wqkv[(size_t)3 * HD * EDIM]; // fused Wq^T|Wk^T|Wv^T
__device__ __nv_bfloat16 g_wo[(size_t)EDIM * HD];
__device__ double g_logits[BATCH * NCLS];

// ---------------------------------------------------------------------------
// 1) Embedding gather -> bf16
// ---------------------------------------------------------------------------
__global__ __launch_bounds__(256) void gather_kernel(
    const int* __restrict__ x, const float* __restrict__ emb)
{
    int row = blockIdx.x;
    int v = x[row];
    int t = threadIdx.x;
    float4 f = ((const float4*)(emb + (size_t)v * EDIM))[t];
    __nv_bfloat162 lo = __floats2bfloat162_rn(f.x, f.y);
    __nv_bfloat162 hi = __floats2bfloat162_rn(f.z, f.w);
    uint2 p;
    p.x = *(uint32_t*)&lo;
    p.y = *(uint32_t*)&hi;
    ((uint2*)(g_hb + (size_t)row * EDIM))[t] = p;
}

// ---------------------------------------------------------------------------
// 1b) Fused weight transpose + convert (grid.z selects which weight)
// ---------------------------------------------------------------------------
__global__ __launch_bounds__(256) void transpose_all_kernel(
    const float* __restrict__ Wq, const float* __restrict__ Wkv,
    const float* __restrict__ Wo,
    __nv_bfloat16* __restrict__ wqkv, __nv_bfloat16* __restrict__ wo)
{
    __shared__ float tile[32][33];
    const float* in; int ldin, coloff; __nv_bfloat16* out;
    switch (blockIdx.z) {
        case 0: in = Wq;  ldin = HD;     coloff = 0;  out = wqkv;                         break;
        case 1: in = Wkv; ldin = 2 * HD; coloff = 0;  out = wqkv + (size_t)HD * EDIM;     break;
        case 2: in = Wkv; ldin = 2 * HD; coloff = HD; out = wqkv + (size_t)2 * HD * EDIM; break;
        default: in = Wo; ldin = EDIM;   coloff = 0;  out = wo;                           break;
    }
    int bx = blockIdx.x * 32;  // n block
    int by = blockIdx.y * 32;  // k block
    int tx = threadIdx.x & 31;
    int ty = threadIdx.x >> 5;
    for (int i = ty; i < 32; i += 8)
        tile[i][tx] = in[(size_t)(by + i) * ldin + coloff + bx + tx];
    __syncthreads();
    for (int i = ty; i < 32; i += 8)
        out[(size_t)(bx + i) * 1024 + by + tx] = __float2bfloat16(tile[tx][i]);
}

// ---------------------------------------------------------------------------
// 2) bf16 tensor-core GEMM (mma.sync). CTA tile 128x128, 256 threads,
//    warp tile 32x64, 3-stage cp.async ring, 2 CTAs/SM. (R5 config — best.)
// ---------------------------------------------------------------------------
#define MT 128
#define NT 128
#define A_BYTES (MT * 128)          // 16 KB per K-chunk of 64
#define B_BYTES (NT * 128)          // 16 KB
#define NCHUNKS 16
#define STAGES 3
#define GEMM_SMEM (STAGES * (A_BYTES + B_BYTES) + 1024)   // 99328

__device__ __forceinline__ void load_chunk(
    uint32_t abuf, uint32_t bbuf,
    const char* Abase, const char* Bbase, int c, int t)
{
#pragma unroll
    for (int i = 0; i < 4; i++) {
        int seg = t + 256 * i;
        int r = seg >> 3, s = seg & 7;
        uint32_t off = SMEM_SWIZZLE_128B((uint32_t)(r * 128 + s * 16));
        cp_async16(abuf + off, Abase + (size_t)r * 2048 + c * 128 + s * 16);
    }
#pragma unroll
    for (int i = 0; i < 4; i++) {
        int seg = t + 256 * i;
        int r = seg >> 3, s = seg & 7;
        uint32_t off = SMEM_SWIZZLE_128B((uint32_t)(r * 128 + s * 16));
        cp_async16(bbuf + off, Bbase + (size_t)r * 2048 + c * 128 + s * 16);
    }
}

template<bool RES>
__global__ __launch_bounds__(256, 2) void gemm_bf16_kernel(
    const __nv_bfloat16* __restrict__ A,
    const __nv_bfloat16* __restrict__ Bt,
    const __nv_bfloat16* __restrict__ Res,
    __nv_bfloat16* __restrict__ D0,
    __nv_bfloat16* __restrict__ D1,
    __nv_bfloat16* __restrict__ D2,
    int nxblocks)
{
    extern __shared__ char smem[];
    uint32_t base = (smem_to_u32(smem) + 1023) & ~1023u;
    uint32_t a_sm[STAGES], b_sm[STAGES];
#pragma unroll
    for (int s = 0; s < STAGES; s++) {
        a_sm[s] = base + s * (A_BYTES + B_BYTES);
        b_sm[s] = a_sm[s] + A_BYTES;
    }

    int t = threadIdx.x;
    int wid = t >> 5, lane = t & 31;
    int mwarp0 = (wid & 3) * 32;
    int nwarp0 = (wid >> 2) * 64;

    // Raster swizzle: group 8 y-blocks per x-stripe so a wave shares B tiles.
    int bid = blockIdx.x;
    int ny = gridDim.y;                  // 512
    int group = bid / (nxblocks * 8);    // which y-octet
    int rem   = bid % (nxblocks * 8);
    int bx = rem % nxblocks;
    int by = group * 8 + (rem / nxblocks);

    size_t row0 = (size_t)by * MT;
    int col0 = bx * NT;
    (void)ny;

    // output buffer selection (fused QKV; NT divides 1024 so no straddle)
    int tgt = col0 >> 10;
    int colc = col0 & 1023;
    __nv_bfloat16* D = (tgt == 0) ? D0 : ((tgt == 1) ? D1 : D2);

    const char* Abase = (const char*)(A + row0 * 1024);
    const char* Bbase = (const char*)(Bt + (size_t)col0 * 1024);

    // per-lane ldmatrix address components
    int g = lane & 7, sel = lane >> 3;
    int mA = mwarp0 + g + (sel & 1) * 8;
    uint32_t aRow[2] = { (uint32_t)(mA * 128), (uint32_t)((mA + 16) * 128) };
    uint32_t aKb = (uint32_t)((sel >> 1) * 16);
    uint32_t aX  = (uint32_t)((mA & 7) << 4);

    int nB = nwarp0 + g + ((sel >> 1) * 8);
    uint32_t bRow[4] = { (uint32_t)(nB * 128), (uint32_t)((nB + 16) * 128),
                         (uint32_t)((nB + 32) * 128), (uint32_t)((nB + 48) * 128) };
    uint32_t bKb = (uint32_t)((sel & 1) * 16);
    uint32_t bX  = (uint32_t)((nB & 7) << 4);

    float acc[2][8][4];
#pragma unroll
    for (int i = 0; i < 2; i++)
#pragma unroll
        for (int j = 0; j < 8; j++)
#pragma unroll
            for (int k = 0; k < 4; k++) acc[i][j][k] = 0.f;

    // prologue: prime 2 stages
    load_chunk(a_sm[0], b_sm[0], Abase, Bbase, 0, t); cp_commit();
    load_chunk(a_sm[1], b_sm[1], Abase, Bbase, 1, t); cp_commit();

    int stage = 0;
    for (int c = 0; c < NCHUNKS; c++) {
        if (c < NCHUNKS - 1) {
            asm volatile("cp.async.wait_group 1;" ::: "memory");
        } else {
            asm volatile("cp.async.wait_group 0;" ::: "memory");
        }
        __syncthreads();
        if (c + 2 < NCHUNKS) {
            int ns = stage + 2; if (ns >= STAGES) ns -= STAGES;
            load_chunk(a_sm[ns], b_sm[ns], Abase, Bbase, c + 2, t);
            cp_commit();
        }

        uint32_t ab = a_sm[stage], bb = b_sm[stage];
#pragma unroll
        for (int s = 0; s < 4; s++) {         // 4 k16 steps per chunk
            uint32_t kb0 = (uint32_t)(s * 32);
            uint32_t afrag[2][4], bfrag[4][4];
#pragma unroll
            for (int mi = 0; mi < 2; mi++)
                ldmx4(afrag[mi], ab + aRow[mi] + ((aKb + kb0) ^ aX));
#pragma unroll
            for (int j = 0; j < 4; j++)
                ldmx4(bfrag[j], bb + bRow[j] + ((bKb + kb0) ^ bX));
#pragma unroll
            for (int mi = 0; mi < 2; mi++)
#pragma unroll
                for (int j = 0; j < 4; j++) {
                    mma16816(acc[mi][2 * j],     afrag[mi], &bfrag[j][0]);
                    mma16816(acc[mi][2 * j + 1], afrag[mi], &bfrag[j][2]);
                }
        }
        stage++; if (stage >= STAGES) stage -= STAGES;
    }

    // Epilogue
#pragma unroll
    for (int mi = 0; mi < 2; mi++) {
        size_t r0 = row0 + mwarp0 + mi * 16 + (lane >> 2);
#pragma unroll
        for (int nj = 0; nj < 8; nj++) {
            int col = colc + nwarp0 + nj * 8 + (lane & 3) * 2;
            float c0 = acc[mi][nj][0], c1 = acc[mi][nj][1];
            float c2 = acc[mi][nj][2], c3 = acc[mi][nj][3];
            if (RES) {
                uint32_t u0 = *(const uint32_t*)(Res + r0 * 1024 + col);
                uint32_t u1 = *(const uint32_t*)(Res + (r0 + 8) * 1024 + col);
                float2 f0 = __bfloat1622float2(*(__nv_bfloat162*)&u0);
                float2 f1 = __bfloat1622float2(*(__nv_bfloat162*)&u1);
                c0 += f0.x; c1 += f0.y; c2 += f1.x; c3 += f1.y;
            }
            __nv_bfloat162 h0 = __floats2bfloat162_rn(c0, c1);
            __nv_bfloat162 h1 = __floats2bfloat162_rn(c2, c3);
            *(uint32_t*)(D + r0 * 1024 + col)       = *(uint32_t*)&h0;
            *(uint32_t*)(D + (r0 + 8) * 1024 + col) = *(uint32_t*)&h1;
        }
    }
}

// ---------------------------------------------------------------------------
// 3) Attention on tensor cores. One warp per (l, n) pair.
// ---------------------------------------------------------------------------
#define ATT_WARPS 8
#define ATT_SMEM (ATT_WARPS * 3 * 4096)   // 96 KB
#define ROWSTRIDE_B (LSEQ * NHEAD * DHEAD * 2)  // batch-row stride in bytes

__global__ __launch_bounds__(256) void attn_kernel()
{
    extern __shared__ char asmem[];
    int t = threadIdx.x, w = t >> 5, lane = t & 31;
    uint32_t wbase = smem_to_u32(asmem) + w * 12288;
    uint32_t qsm = wbase, ksm = wbase + 4096, vsm = wbase + 8192;

    int pair = blockIdx.x * ATT_WARPS + w;
    int l = pair >> 4, n = pair & 15;
    size_t ebase = ((size_t)l * NHEAD + n) * DHEAD;
    const char* qg = (const char*)(g_qb + ebase);
    const char* kg = (const char*)(g_kb + ebase);
    const char* vg = (const char*)(g_vb + ebase);

#pragma unroll
    for (int i = 0; i < 8; i++) {
        int s = lane + 32 * i;
        int row = s >> 3, sub = s & 7;
        size_t go = (size_t)row * ROWSTRIDE_B + sub * 16;
        uint32_t so = SMEM_SWIZZLE_128B((uint32_t)(row * 128 + sub * 16));
        cp_async16(qsm + so, qg + go);
        cp_async16(ksm + so, kg + go);
        cp_async16(vsm + so, vg + go);
    }
    cp_commit();
    asm volatile("cp.async.wait_group 0;" ::: "memory");
    __syncwarp();

    int g8 = lane & 7, sel = lane >> 3;

    // ---- S = Q K^T ----
    float c[2][4][4];
#pragma unroll
    for (int mi = 0; mi < 2; mi++)
#pragma unroll
        for (int j = 0; j < 4; j++)
#pragma unroll
            for (int k = 0; k < 4; k++) c[mi][j][k] = 0.f;

#pragma unroll
    for (int kc = 0; kc < 4; kc++) {
        uint32_t kb = kc * 32;
        uint32_t af[2][4], bfr[2][4];
#pragma unroll
        for (int mi = 0; mi < 2; mi++) {
            int row = mi * 16 + g8 + (sel & 1) * 8;
            uint32_t off = row * 128 + ((kb + (sel >> 1) * 16) ^ ((row & 7) << 4));
            ldmx4(af[mi], qsm + off);
        }
#pragma unroll
        for (int nj2 = 0; nj2 < 2; nj2++) {
            int row = nj2 * 16 + g8 + (sel >> 1) * 8;
            uint32_t off = row * 128 + ((kb + (sel & 1) * 16) ^ ((row & 7) << 4));
            ldmx4(bfr[nj2], ksm + off);
        }
#pragma unroll
        for (int mi = 0; mi < 2; mi++)
#pragma unroll
            for (int nj2 = 0; nj2 < 2; nj2++) {
                mma16816(c[mi][2 * nj2],     af[mi], &bfr[nj2][0]);
                mma16816(c[mi][2 * nj2 + 1], af[mi], &bfr[nj2][2]);
            }
    }

    // ---- softmax ----
    float inv0[2], inv1[2];
#pragma unroll
    for (int mi = 0; mi < 2; mi++) {
        float m0 = -FLT_MAX, m1 = -FLT_MAX;
#pragma unroll
        for (int j = 0; j < 4; j++) {
#pragma unroll
            for (int k = 0; k < 4; k++) c[mi][j][k] *= 0.125f;
            m0 = fmaxf(m0, fmaxf(c[mi][j][0], c[mi][j][1]));
            m1 = fmaxf(m1, fmaxf(c[mi][j][2], c[mi][j][3]));
        }
        m0 = fmaxf(m0, __shfl_xor_sync(0xffffffffu, m0, 1));
        m0 = fmaxf(m0, __shfl_xor_sync(0xffffffffu, m0, 2));
        m1 = fmaxf(m1, __shfl_xor_sync(0xffffffffu, m1, 1));
        m1 = fmaxf(m1, __shfl_xor_sync(0xffffffffu, m1, 2));
        float s0 = 0.f, s1 = 0.f;
#pragma unroll
        for (int j = 0; j < 4; j++) {
            c[mi][j][0] = __expf(c[mi][j][0] - m0);
            c[mi][j][1] = __expf(c[mi][j][1] - m0);
            c[mi][j][2] = __expf(c[mi][j][2] - m1);
            c[mi][j][3] = __expf(c[mi][j][3] - m1);
            s0 += c[mi][j][0] + c[mi][j][1];
            s1 += c[mi][j][2] + c[mi][j][3];
        }
        s0 += __shfl_xor_sync(0xffffffffu, s0, 1);
        s0 += __shfl_xor_sync(0xffffffffu, s0, 2);
        s1 += __shfl_xor_sync(0xffffffffu, s1, 1);
        s1 += __shfl_xor_sync(0xffffffffu, s1, 2);
        inv0[mi] = 1.f / s0;
        inv1[mi] = 1.f / s1;
    }

    // ---- pack P ----
    uint32_t pf[2][2][4];
#pragma unroll
    for (int mi = 0; mi < 2; mi++)
#pragma unroll
        for (int kc = 0; kc < 2; kc++) {
            __nv_bfloat162 x0 = __floats2bfloat162_rn(c[mi][2 * kc][0],     c[mi][2 * kc][1]);
            __nv_bfloat162 x1 = __floats2bfloat162_rn(c[mi][2 * kc][2],     c[mi][2 * kc][3]);
            __nv_bfloat162 x2 = __floats2bfloat162_rn(c[mi][2 * kc + 1][0], c[mi][2 * kc + 1][1]);
            __nv_bfloat162 x3 = __floats2bfloat162_rn(c[mi][2 * kc + 1][2], c[mi][2 * kc + 1][3]);
            pf[mi][kc][0] = *(uint32_t*)&x0;
            pf[mi][kc][1] = *(uint32_t*)&x1;
            pf[mi][kc][2] = *(uint32_t*)&x2;
            pf[mi][kc][3] = *(uint32_t*)&x3;
        }

    // ---- att = P V ----
    float cv[2][8][4];
#pragma unroll
    for (int mi = 0; mi < 2; mi++)
#pragma unroll
        for (int j = 0; j < 8; j++)
#pragma unroll
            for (int k = 0; k < 4; k++) cv[mi][j][k] = 0.f;

#pragma unroll
    for (int kc = 0; kc < 2; kc++) {
#pragma unroll
        for (int dj2 = 0; dj2 < 4; dj2++) {
            int row = kc * 16 + g8 + (sel & 1) * 8;
            uint32_t colb = dj2 * 32 + (sel >> 1) * 16;
            uint32_t off = row * 128 + (colb ^ ((row & 7) << 4));
            uint32_t bv[4];
            ldmx4t(bv, vsm + off);
#pragma unroll
            for (int mi = 0; mi < 2; mi++) {
                mma16816(cv[mi][2 * dj2],     pf[mi][kc], &bv[0]);
                mma16816(cv[mi][2 * dj2 + 1], pf[mi][kc], &bv[2]);
            }
        }
    }

    // ---- normalize + store ----
    int r = lane >> 2, cq = (lane & 3) * 2;
#pragma unroll
    for (int mi = 0; mi < 2; mi++) {
        int i0 = mi * 16 + r;
        __nv_bfloat16* o0 = g_qb + ebase + (size_t)i0 * (LSEQ * NHEAD * DHEAD);
        __nv_bfloat16* o1 = o0 + (size_t)8 * (LSEQ * NHEAD * DHEAD);
#pragma unroll
        for (int dj = 0; dj < 8; dj++) {
            int col = dj * 8 + cq;
            __nv_bfloat162 h0 = __floats2bfloat162_rn(cv[mi][dj][0] * inv0[mi],
                                                      cv[mi][dj][1] * inv0[mi]);
            __nv_bfloat162 h1 = __floats2bfloat162_rn(cv[mi][dj][2] * inv1[mi],
                                                      cv[mi][dj][3] * inv1[mi]);
            *(uint32_t*)(o0 + col) = *(uint32_t*)&h0;
            *(uint32_t*)(o1 + col) = *(uint32_t*)&h1;
        }
    }
}

// ---------------------------------------------------------------------------
// 4) Logits
// ---------------------------------------------------------------------------
__global__ void zero_logits_kernel()
{
    if (threadIdx.x < BATCH * NCLS) g_logits[threadIdx.x] = 0.0;
}

__global__ __launch_bounds__(256) void logits_kernel(const float* __restrict__ Wf)
{
    const int CHUNK = 512;
    int i0 = blockIdx.x * CHUNK;
    int t = threadIdx.x;

    float acc[64];
#pragma unroll
    for (int k = 0; k < 64; k++) acc[k] = 0.f;

    for (int s = 0; s < CHUNK; s += 256) {
        int ii = i0 + s + t;
        float w0 = Wf[(size_t)ii * 2];
        float w1 = Wf[(size_t)ii * 2 + 1];
#pragma unroll
        for (int b = 0; b < 32; b++) {
            float v = __bfloat162float(g_ob[(size_t)b * FLAT + ii]);
            acc[2 * b]     += v * w0;
            acc[2 * b + 1] += v * w1;
        }
    }

#pragma unroll
    for (int k = 0; k < 64; k++) {
        float v = acc[k];
        v += __shfl_down_sync(0xffffffffu, v, 16);
        v += __shfl_down_sync(0xffffffffu, v, 8);
        v += __shfl_down_sync(0xffffffffu, v, 4);
        v += __shfl_down_sync(0xffffffffu, v, 2);
        v += __shfl_down_sync(0xffffffffu, v, 1);
        acc[k] = v;
    }

    __shared__ float sacc[64];
    if (t < 64) sacc[t] = 0.f;
    __syncthreads();
    if ((t & 31) == 0) {
#pragma unroll
        for (int k = 0; k < 64; k++) atomicAdd(&sacc[k], acc[k]);
    }
    __syncthreads();
    if (t < 64) atomicAdd(&g_logits[t], (double)sacc[t]);
}

// ---------------------------------------------------------------------------
// 5) Loss
// ---------------------------------------------------------------------------
__global__ void loss_kernel(const int* __restrict__ y,
                            const float* __restrict__ bf,
                            float* __restrict__ out)
{
    if (threadIdx.x != 0 || blockIdx.x != 0) return;
    double s = 0.0;
    double b0 = (double)bf[0], b1 = (double)bf[1];
    for (int b = 0; b < BATCH; b++) {
        double l0 = g_logits[2 * b]     + b0;
        double l1 = g_logits[2 * b + 1] + b1;
        double m  = l0 > l1 ? l0 : l1;
        double lse = m + log(exp(l0 - m) + exp(l1 - m));
        double lp  = (y[b] == 0 ? l0 : l1) - lse;
        s += lp;
    }
    out[0] = (float)(-s / (double)BATCH);
}

// ---------------------------------------------------------------------------
// Launch
// ---------------------------------------------------------------------------
extern "C" void kernel_launch(void* const* d_in, const int* in_sizes, int n_in,
                              void* d_out, int out_size)
{
    const int*   x     = (const int*)d_in[0];
    const int*   y     = (const int*)d_in[1];
    const float* emb   = (const float*)d_in[2];
    const float* Wq    = (const float*)d_in[3];
    const float* Wkv   = (const float*)d_in[4];
    const float* Wo    = (const float*)d_in[5];
    const float* Wf    = (const float*)d_in[6];
    const float* bf    = (const float*)d_in[7];
    float* out = (float*)d_out;

    __nv_bfloat16 *p_hb, *p_qb, *p_kb, *p_vb, *p_ob, *p_wqkv, *p_wo;
    cudaGetSymbolAddress((void**)&p_hb,   g_hb);
    cudaGetSymbolAddress((void**)&p_qb,   g_qb);
    cudaGetSymbolAddress((void**)&p_kb,   g_kb);
    cudaGetSymbolAddress((void**)&p_vb,   g_vb);
    cudaGetSymbolAddress((void**)&p_ob,   g_ob);
    cudaGetSymbolAddress((void**)&p_wqkv, g_wqkv);
    cudaGetSymbolAddress((void**)&p_wo,   g_wo);

    cudaFuncSetAttribute(gemm_bf16_kernel<false>,
                         cudaFuncAttributeMaxDynamicSharedMemorySize, GEMM_SMEM);
    cudaFuncSetAttribute(gemm_bf16_kernel<true>,
                         cudaFuncAttributeMaxDynamicSharedMemorySize, GEMM_SMEM);
    cudaFuncSetAttribute(attn_kernel,
                         cudaFuncAttributeMaxDynamicSharedMemorySize, ATT_SMEM);

    // 1) gather + fused weight prep
    gather_kernel<<<ROWS, 256>>>(x, emb);
    dim3 tgrid(32, 32, 4), tblk(256);
    transpose_all_kernel<<<tgrid, tblk>>>(Wq, Wkv, Wo, p_wqkv, p_wo);

    // 2) fused QKV projection: one GEMM, N = 3072 (1D grid, swizzled raster)
    {
        int nx = 3 * EDIM / NT;              // 24
        dim3 grid(nx * (ROWS / MT), 1);      // 12288 CTAs
        // gridDim.y used only for model; pass nx for deswizzle
        gemm_bf16_kernel<false><<<dim3(nx * (ROWS / MT), 1), 256, GEMM_SMEM>>>(
            p_hb, p_wqkv, nullptr, p_qb, p_kb, p_vb, nx);
        (void)grid;
    }

    // 3) attention (tensor cores; in place: g_qb <- att)
    attn_kernel<<<LSEQ * NHEAD / ATT_WARPS, 256, ATT_SMEM>>>();

    // 4) out = h + att @ Wo
    {
        int nx = EDIM / NT;                  // 8
        gemm_bf16_kernel<true><<<dim3(nx * (ROWS / MT), 1), 256, GEMM_SMEM>>>(
            p_qb, p_wo, p_hb, p_ob, p_ob, p_ob, nx);
    }

    // 5) logits + loss
    zero_logits_kernel<<<1, 64>>>();
    logits_kernel<<<FLAT / 512, 256>>>(Wf);
    loss_kernel<<<1, 32>>>(y, bf, out);
}